// round 3
// baseline (speedup 1.0000x reference)
#include <cuda_runtime.h>

// Problem constants
#define E_DIM   1024
#define N_HEADS 16
#define HDIM    64
#define NB      4
#define SEQ     2048
#define BH_TOT  (NB * N_HEADS)   // 64
#define M_ROWS  (NB * SEQ)       // 8192

// Scratch (device globals: no allocation allowed)
__device__ float g_q[BH_TOT * SEQ * HDIM];   // [B,H,T,D], pre-scaled by D^-0.5
__device__ float g_k[BH_TOT * SEQ * HDIM];
__device__ float g_v[BH_TOT * SEQ * HDIM];
__device__ float g_ctx[M_ROWS * E_DIM];      // [B,T,H*D]

// ---------------------------------------------------------------------------
// NT GEMM: C[m,n] = sum_k A[m,k] * W[n,k] + bias[n]
// A: [M,K] row-major, W: [N,K] row-major. 128x128 tile, BK=16, 256 threads,
// 8x8 per thread (split 4+4 fragments for conflict-free smem reads).
// mode 0: store to C [M,N].  mode 1: scatter QKV into g_q/g_k/g_v (q *= 0.125).
// A == nullptr means "read from g_ctx".
// ---------------------------------------------------------------------------
__global__ __launch_bounds__(256) void gemm_nt(
    const float* __restrict__ A, const float* __restrict__ W,
    const float* __restrict__ bias, float* __restrict__ C,
    int K, int N, int mode)
{
    __shared__ float As[16][132];   // [k][m], pad to 132 for store-conflict relief
    __shared__ float Bs[16][132];   // [k][n]

    const float* Ain = A ? A : g_ctx;

    int t  = threadIdx.x;
    int ty = t >> 4;          // 0..15
    int tx = t & 15;          // 0..15
    int lrow = t >> 1;        // 0..127  (load row within tile)
    int lcol = (t & 1) << 3;  // 0 or 8  (load k-offset)

    const float* Ap = Ain + (size_t)(blockIdx.y * 128 + lrow) * K + lcol;
    const float* Wp = W   + (size_t)(blockIdx.x * 128 + lrow) * K + lcol;

    float acc[8][8];
#pragma unroll
    for (int i = 0; i < 8; i++)
#pragma unroll
        for (int j = 0; j < 8; j++) acc[i][j] = 0.f;

    for (int k0 = 0; k0 < K; k0 += 16) {
        float4 a0 = *(const float4*)(Ap + k0);
        float4 a1 = *(const float4*)(Ap + k0 + 4);
        float4 b0 = *(const float4*)(Wp + k0);
        float4 b1 = *(const float4*)(Wp + k0 + 4);
        __syncthreads();  // previous tile's compute done before overwrite
        As[lcol + 0][lrow] = a0.x; As[lcol + 1][lrow] = a0.y;
        As[lcol + 2][lrow] = a0.z; As[lcol + 3][lrow] = a0.w;
        As[lcol + 4][lrow] = a1.x; As[lcol + 5][lrow] = a1.y;
        As[lcol + 6][lrow] = a1.z; As[lcol + 7][lrow] = a1.w;
        Bs[lcol + 0][lrow] = b0.x; Bs[lcol + 1][lrow] = b0.y;
        Bs[lcol + 2][lrow] = b0.z; Bs[lcol + 3][lrow] = b0.w;
        Bs[lcol + 4][lrow] = b1.x; Bs[lcol + 5][lrow] = b1.y;
        Bs[lcol + 6][lrow] = b1.z; Bs[lcol + 7][lrow] = b1.w;
        __syncthreads();
#pragma unroll
        for (int k = 0; k < 16; k++) {
            float af[8], bf[8];
            *(float4*)&af[0] = *(const float4*)&As[k][ty * 4];
            *(float4*)&af[4] = *(const float4*)&As[k][64 + ty * 4];
            *(float4*)&bf[0] = *(const float4*)&Bs[k][tx * 4];
            *(float4*)&bf[4] = *(const float4*)&Bs[k][64 + tx * 4];
#pragma unroll
            for (int i = 0; i < 8; i++)
#pragma unroll
                for (int j = 0; j < 8; j++)
                    acc[i][j] = fmaf(af[i], bf[j], acc[i][j]);
        }
    }

    int rbase = blockIdx.y * 128;
    int cbase = blockIdx.x * 128;
#pragma unroll
    for (int i = 0; i < 8; i++) {
        int m = rbase + ((i & 4) ? 64 : 0) + ty * 4 + (i & 3);
#pragma unroll
        for (int j = 0; j < 8; j++) {
            int n = cbase + ((j & 4) ? 64 : 0) + tx * 4 + (j & 3);
            float val = acc[i][j] + bias[n];
            if (mode == 0) {
                C[(size_t)m * N + n] = val;
            } else {
                int part = n >> 10;       // 0:q 1:k 2:v
                int r    = n & 1023;
                int h    = r >> 6;
                int d    = r & 63;
                int b    = m >> 11;       // /2048
                int tt   = m & 2047;
                int idx  = ((b * N_HEADS + h) * SEQ + tt) * HDIM + d;
                if (part == 0)      g_q[idx] = val * 0.125f;  // fold D^-0.5
                else if (part == 1) g_k[idx] = val;
                else                g_v[idx] = val;
            }
        }
    }
}

// ---------------------------------------------------------------------------
// Flash attention, fp32. One block per (q-tile of 64 rows, bh).
// Br = Bc = 64, online softmax, 256 threads, each owns a 4x4 fragment of
// S (64x64) and of O (64x64).
// ---------------------------------------------------------------------------
#define PADW 68
#define ATTN_SMEM_BYTES ((4 * 64 * PADW + 3 * 64) * 4)

__global__ __launch_bounds__(256) void attn_kernel()
{
    extern __shared__ float sm[];
    float* Qs   = sm;                  // [64][PADW]
    float* Ks   = Qs + 64 * PADW;
    float* Vs   = Ks + 64 * PADW;
    float* Ss   = Vs + 64 * PADW;
    float* rowm = Ss + 64 * PADW;      // [64]
    float* rowl = rowm + 64;
    float* rowa = rowl + 64;

    int t  = threadIdx.x;
    int ty = t >> 4, tx = t & 15;
    int bh = blockIdx.y;
    int q0 = blockIdx.x * 64;

    // Load Q tile (64x64)
    const float* qbase = g_q + (size_t)(bh * SEQ + q0) * HDIM;
#pragma unroll
    for (int q = 0; q < 4; q++) {
        int id = t + 256 * q;
        int r  = id >> 4;
        int c  = (id & 15) << 2;
        *(float4*)&Qs[r * PADW + c] = *(const float4*)(qbase + r * HDIM + c);
    }
    if (t < 64) { rowm[t] = -1e30f; rowl[t] = 0.f; }

    float o[4][4];
#pragma unroll
    for (int i = 0; i < 4; i++)
#pragma unroll
        for (int j = 0; j < 4; j++) o[i][j] = 0.f;

    for (int jt = 0; jt < SEQ / 64; jt++) {
        __syncthreads();  // PV of previous tile done before K/V overwrite
        const float* kbase = g_k + (size_t)(bh * SEQ + jt * 64) * HDIM;
        const float* vbase = g_v + (size_t)(bh * SEQ + jt * 64) * HDIM;
#pragma unroll
        for (int q = 0; q < 4; q++) {
            int id = t + 256 * q;
            int r  = id >> 4;
            int c  = (id & 15) << 2;
            *(float4*)&Ks[r * PADW + c] = *(const float4*)(kbase + r * HDIM + c);
            *(float4*)&Vs[r * PADW + c] = *(const float4*)(vbase + r * HDIM + c);
        }
        __syncthreads();

        // S = Q @ K^T  (thread (ty,tx): rows ty*4.., cols tx*4..)
        float s[4][4];
#pragma unroll
        for (int i = 0; i < 4; i++)
#pragma unroll
            for (int j = 0; j < 4; j++) s[i][j] = 0.f;

#pragma unroll 4
        for (int k = 0; k < 64; k += 4) {
            float qf[4][4], kf[4][4];
#pragma unroll
            for (int i = 0; i < 4; i++)
                *(float4*)qf[i] = *(const float4*)&Qs[(ty * 4 + i) * PADW + k];
#pragma unroll
            for (int i = 0; i < 4; i++)
                *(float4*)kf[i] = *(const float4*)&Ks[(tx * 4 + i) * PADW + k];
#pragma unroll
            for (int i = 0; i < 4; i++)
#pragma unroll
                for (int j = 0; j < 4; j++)
#pragma unroll
                    for (int kk = 0; kk < 4; kk++)
                        s[i][j] = fmaf(qf[i][kk], kf[j][kk], s[i][j]);
        }
#pragma unroll
        for (int i = 0; i < 4; i++)
            *(float4*)&Ss[(ty * 4 + i) * PADW + tx * 4] =
                make_float4(s[i][0], s[i][1], s[i][2], s[i][3]);
        __syncthreads();

        // Online softmax stats: 4 threads per row, 16 cols each
        {
            int r = t >> 2, p = t & 3;
            float* srow = &Ss[r * PADW + p * 16];
            float mx = srow[0];
#pragma unroll
            for (int c = 1; c < 16; c++) mx = fmaxf(mx, srow[c]);
            mx = fmaxf(mx, __shfl_xor_sync(0xffffffffu, mx, 1));
            mx = fmaxf(mx, __shfl_xor_sync(0xffffffffu, mx, 2));
            float m_old = rowm[r];
            float m_new = fmaxf(m_old, mx);
            float sum = 0.f;
#pragma unroll
            for (int c = 0; c < 16; c++) {
                float e = __expf(srow[c] - m_new);
                srow[c] = e;
                sum += e;
            }
            sum += __shfl_xor_sync(0xffffffffu, sum, 1);
            sum += __shfl_xor_sync(0xffffffffu, sum, 2);
            if (p == 0) {
                float alpha = __expf(m_old - m_new);  // 0 on first tile
                rowa[r] = alpha;
                rowm[r] = m_new;
                rowl[r] = rowl[r] * alpha + sum;
            }
        }
        __syncthreads();

        // O = O*alpha + P @ V
        float alpha4[4];
#pragma unroll
        for (int i = 0; i < 4; i++) alpha4[i] = rowa[ty * 4 + i];
#pragma unroll
        for (int i = 0; i < 4; i++)
#pragma unroll
            for (int j = 0; j < 4; j++) o[i][j] *= alpha4[i];

#pragma unroll 4
        for (int k = 0; k < 64; k += 4) {
            float pf[4][4], vf[4][4];
#pragma unroll
            for (int i = 0; i < 4; i++)
                *(float4*)pf[i] = *(const float4*)&Ss[(ty * 4 + i) * PADW + k];
#pragma unroll
            for (int kk = 0; kk < 4; kk++)
                *(float4*)vf[kk] = *(const float4*)&Vs[(k + kk) * PADW + tx * 4];
#pragma unroll
            for (int i = 0; i < 4; i++)
#pragma unroll
                for (int j = 0; j < 4; j++) {
                    o[i][j] = fmaf(pf[i][0], vf[0][j], o[i][j]);
                    o[i][j] = fmaf(pf[i][1], vf[1][j], o[i][j]);
                    o[i][j] = fmaf(pf[i][2], vf[2][j], o[i][j]);
                    o[i][j] = fmaf(pf[i][3], vf[3][j], o[i][j]);
                }
        }
    }

    // Normalize and write ctx in [B,T,H,D] (== [B,T,E]) layout
    int b = bh >> 4, h = bh & 15;
#pragma unroll
    for (int i = 0; i < 4; i++) {
        float inv = 1.0f / rowl[ty * 4 + i];
        int tt = q0 + ty * 4 + i;
        float* dst = g_ctx + ((size_t)(b * SEQ + tt) * N_HEADS + h) * HDIM + tx * 4;
        *(float4*)dst = make_float4(o[i][0] * inv, o[i][1] * inv,
                                    o[i][2] * inv, o[i][3] * inv);
    }
}

// ---------------------------------------------------------------------------
extern "C" void kernel_launch(void* const* d_in, const int* in_sizes, int n_in,
                              void* d_out, int out_size)
{
    const float* query = (const float*)d_in[0];   // [4,2048,1024]
    const float* in_w  = (const float*)d_in[1];   // [3072,1024]
    const float* in_b  = (const float*)d_in[2];   // [3072]
    const float* out_w = (const float*)d_in[3];   // [1024,1024]
    const float* out_b = (const float*)d_in[4];   // [1024]
    float* out = (float*)d_out;                   // [4,2048,1024]

    cudaFuncSetAttribute(attn_kernel,
                         cudaFuncAttributeMaxDynamicSharedMemorySize,
                         ATTN_SMEM_BYTES);

    // 1) QKV projection + scatter to [B,H,T,D] (q scaled)
    gemm_nt<<<dim3(3 * E_DIM / 128, M_ROWS / 128), 256>>>(
        query, in_w, in_b, nullptr, E_DIM, 3 * E_DIM, 1);

    // 2) Flash attention -> g_ctx
    attn_kernel<<<dim3(SEQ / 64, BH_TOT), 256, ATTN_SMEM_BYTES>>>();

    // 3) Output projection -> d_out
    gemm_nt<<<dim3(E_DIM / 128, M_ROWS / 128), 256>>>(
        nullptr, out_w, out_b, out, E_DIM, E_DIM, 0);
}